// round 17
// baseline (speedup 1.0000x reference)
#include <cuda_runtime.h>
#include <cuda_fp16.h>
#include <cstdint>

// ---------------------------------------------------------------------------
// NNUE: out[b] = tanh(relu(relu((sum_f emb[idx[f,b]]) @ w1^T + b1) @ w2^T + b2) @ w3^T + b3)
//
// K1: g_tbl = emb @ w1^T via mma.sync m16n8k16 fp16 single-term.
//     A fragments loaded DIRECTLY from gmem (per-lane LDG.64 + cvt)
//     using the canonical fragment layout; A rows are warp-private so no
//     smem staging, no ldmatrix-A, zero in-loop barriers. B resident in
//     static smem via ldmatrix.
// K2 (R15, frozen): warp-coalesced gather + smem-broadcast MLP.
// (Identical resubmission of R16 — prior bench died on container infra.)
// ---------------------------------------------------------------------------

#define FULLMASK 0xffffffffu

constexpr int INPUT_DIM = 49152;
constexpr int EMB_DIM   = 256;
constexpr int BATCH     = 16384;

__device__ __half g_tbl[INPUT_DIM * 32];

__device__ __forceinline__ uint32_t smem_u32(const void* p) {
    uint32_t a;
    asm("{ .reg .u64 t; cvta.to.shared.u64 t, %1; cvt.u32.u64 %0, t; }" : "=r"(a) : "l"(p));
    return a;
}
__device__ __forceinline__ void ldmat_x4(uint32_t r[4], uint32_t addr) {
    asm volatile("ldmatrix.sync.aligned.m8n8.x4.shared.b16 {%0,%1,%2,%3}, [%4];"
                 : "=r"(r[0]), "=r"(r[1]), "=r"(r[2]), "=r"(r[3]) : "r"(addr));
}
__device__ __forceinline__ void mma_f16(float d[4], const uint32_t a[4],
                                        uint32_t b0, uint32_t b1) {
    asm volatile("mma.sync.aligned.m16n8k16.row.col.f32.f16.f16.f32 "
                 "{%0,%1,%2,%3}, {%4,%5,%6,%7}, {%8,%9}, {%0,%1,%2,%3};"
                 : "+f"(d[0]), "+f"(d[1]), "+f"(d[2]), "+f"(d[3])
                 : "r"(a[0]), "r"(a[1]), "r"(a[2]), "r"(a[3]), "r"(b0), "r"(b1));
}
__device__ __forceinline__ uint32_t cvt2h(float x, float y) {
    __half2 h = __float22half2_rn(make_float2(x, y));
    return *(uint32_t*)&h;
}

// ---------------------------------------------------------------------------
// Kernel 1.  CTA: 128 threads = 4 warps; 128 rows; grid 384.
// Warp w owns rows w*32..+31 (2 m16 tiles). Loop: 16 k-steps of 16, no
// barriers. Per k-step per mt: 4 LDG.64 (fp32 pairs) + 4 cvt -> A frag;
// B frags via 2 ldmatrix.x4 from resident smem; 8 HMMA.
// Fragment layout (m16n8k16 row-major A): g = lane>>2, t = lane&3:
//   a0=(g, 2t) a1=(g+8, 2t) a2=(g, 2t+8) a3=(g+8, 2t+8).
// ---------------------------------------------------------------------------
constexpr int B_STRIDE = 528;   // bytes per B row: 256 fp16 = 512 + 16 pad
constexpr int SZ_B = 32 * B_STRIDE;                   // 16896

__global__ __launch_bounds__(128)
void k1_precompute(const float* __restrict__ emb, const float* __restrict__ w1) {
    __shared__ __align__(16) char sB[SZ_B];

    const int tid  = threadIdx.x;
    const int wid  = tid >> 5;
    const int lane = tid & 31;
    const int rowBase = blockIdx.x * 128;

    // ---- Prologue: convert w1 (32x256) to fp16 in smem ----
    {
        const float4* src = (const float4*)w1;
        for (int i = tid; i < 2048; i += 128) {
            const float4 v = src[i];
            const int n = i >> 6;
            const int k = (i & 63) * 4;
            *(uint2*)(sB + n * B_STRIDE + k * 2) =
                make_uint2(cvt2h(v.x, v.y), cvt2h(v.z, v.w));
        }
    }
    __syncthreads();            // the only barrier in the kernel

    const int g = lane >> 2;
    const int t = lane & 3;

    // Base pointer for this lane's a0 element of m-tile 0.
    const float* a00 = emb + (size_t)(rowBase + wid * 32 + g) * EMB_DIM + 2 * t;

    const int bN0 = (lane & 7) + ((lane >> 4) & 1) * 8;
    const uint32_t bKoff = (uint32_t)(((lane >> 3) & 1) * 16);
    const uint32_t bBase0 = smem_u32(sB) + (uint32_t)(bN0 * B_STRIDE) + bKoff;
    const uint32_t bBase1 = bBase0 + 16 * B_STRIDE;

    float d[2][4][4];
#pragma unroll
    for (int mt = 0; mt < 2; mt++)
#pragma unroll
        for (int nt = 0; nt < 4; nt++)
#pragma unroll
            for (int r = 0; r < 4; r++) d[mt][nt][r] = 0.0f;

#pragma unroll 4
    for (int ks = 0; ks < 16; ++ks) {
        const int ko = ks * 16;                        // fp32 col offset
        uint32_t b01[4], b23[4];
        ldmat_x4(b01, bBase0 + (uint32_t)(ks * 32));
        ldmat_x4(b23, bBase1 + (uint32_t)(ks * 32));

#pragma unroll
        for (int mt = 0; mt < 2; mt++) {
            const float* base = a00 + (size_t)mt * 16 * EMB_DIM + ko;
            const float2 v0 = *(const float2*)(base);                    // (g,    2t)
            const float2 v1 = *(const float2*)(base + 8 * EMB_DIM);      // (g+8,  2t)
            const float2 v2 = *(const float2*)(base + 8);                // (g,    2t+8)
            const float2 v3 = *(const float2*)(base + 8 * EMB_DIM + 8);  // (g+8,  2t+8)
            uint32_t a[4];
            a[0] = cvt2h(v0.x, v0.y);
            a[1] = cvt2h(v1.x, v1.y);
            a[2] = cvt2h(v2.x, v2.y);
            a[3] = cvt2h(v3.x, v3.y);

            mma_f16(d[mt][0], a, b01[0], b01[1]);
            mma_f16(d[mt][1], a, b01[2], b01[3]);
            mma_f16(d[mt][2], a, b23[0], b23[1]);
            mma_f16(d[mt][3], a, b23[2], b23[3]);
        }
    }

    // ---- Epilogue: D fragments -> fp16 g_tbl ----
    const int cp = (lane & 3) * 2;
#pragma unroll
    for (int mt = 0; mt < 2; mt++) {
        const int r0 = rowBase + wid * 32 + mt * 16 + g;
#pragma unroll
        for (int nt = 0; nt < 4; nt++) {
            const int col = nt * 8 + cp;
            *(__half2*)&g_tbl[(size_t)r0 * 32 + col] =
                __float22half2_rn(make_float2(d[mt][nt][0], d[mt][nt][1]));
            *(__half2*)&g_tbl[(size_t)(r0 + 8) * 32 + col] =
                __float22half2_rn(make_float2(d[mt][nt][2], d[mt][nt][3]));
        }
    }
}

// ---------------------------------------------------------------------------
// Kernel 2 (R15 verbatim): 16 elems/block, 256 threads, grid 1024.
// ---------------------------------------------------------------------------
__global__ __launch_bounds__(256)
void k2_forward(const int* __restrict__ indices,
                const float* __restrict__ b1,
                const float* __restrict__ w2,
                const float* __restrict__ b2,
                const float* __restrict__ w3,
                const float* __restrict__ b3,
                float* __restrict__ out) {
    __shared__ __align__(16) float w2s[32 * 36];
    __shared__ float w3s[32];
    __shared__ float b1s[32];
    __shared__ __align__(8)  int   idx_s[16][34];
    __shared__ __align__(16) float h1s[16][36];

    const int tid = threadIdx.x;
    const int b0 = blockIdx.x * 16;

    for (int t = tid; t < 1024; t += 256)
        w2s[(t >> 5) * 36 + (t & 31)] = w2[t];
    if (tid < 32) { w3s[tid] = w3[tid]; b1s[tid] = b1[tid]; }
    for (int t = tid; t < 512; t += 256) {
        const int f = t >> 4, e = t & 15;
        idx_s[e][f] = indices[f * BATCH + b0 + e];
    }
    __syncthreads();

    const int lane = tid & 31;
    const int half = lane >> 4;
    const int l16  = lane & 15;
    const int e0 = (tid >> 5) * 2;

    const char* gt = (const char*)g_tbl;
    const uint32_t colOff = (uint32_t)(l16 * 4);

    const int2* ia2 = (const int2*)idx_s[e0];
    const int2* ib2 = (const int2*)idx_s[e0 + 1];
    float2 accA = make_float2(0.f, 0.f);
    float2 accB = make_float2(0.f, 0.f);
#pragma unroll
    for (int p = 0; p < 16; ++p) {
        const int2 iA = ia2[p];
        const int2 iB = ib2[p];
        const int idA = half ? iA.y : iA.x;
        const int idB = half ? iB.y : iB.x;
        const __half2 va = *(const __half2*)(gt + ((size_t)idA << 6) + colOff);
        const __half2 vb = *(const __half2*)(gt + ((size_t)idB << 6) + colOff);
        const float2 fa = __half22float2(va);
        const float2 fb = __half22float2(vb);
        accA.x += fa.x; accA.y += fa.y;
        accB.x += fb.x; accB.y += fb.y;
    }
    accA.x += __shfl_xor_sync(FULLMASK, accA.x, 16);
    accA.y += __shfl_xor_sync(FULLMASK, accA.y, 16);
    accB.x += __shfl_xor_sync(FULLMASK, accB.x, 16);
    accB.y += __shfl_xor_sync(FULLMASK, accB.y, 16);

    const float2 b1p = make_float2(b1s[2 * l16], b1s[2 * l16 + 1]);
    const float2 h1a = make_float2(fmaxf(accA.x + b1p.x, 0.f), fmaxf(accA.y + b1p.y, 0.f));
    const float2 h1b = make_float2(fmaxf(accB.x + b1p.x, 0.f), fmaxf(accB.y + b1p.y, 0.f));

    const float2 myh1 = half ? h1b : h1a;
    *(float2*)&h1s[e0 + half][2 * l16] = myh1;
    __syncwarp();

    float4 wrow[8];
#pragma unroll
    for (int i = 0; i < 8; i++)
        wrow[i] = *(const float4*)&w2s[lane * 36 + i * 4];
    const float* wr = (const float*)wrow;

    float h2a = b2[lane], h2b = h2a;
#pragma unroll
    for (int k4 = 0; k4 < 8; ++k4) {
        const float4 ha = *(const float4*)&h1s[e0][k4 * 4];
        const float4 hb = *(const float4*)&h1s[e0 + 1][k4 * 4];
        h2a = fmaf(ha.x, wr[4 * k4 + 0], h2a);
        h2a = fmaf(ha.y, wr[4 * k4 + 1], h2a);
        h2a = fmaf(ha.z, wr[4 * k4 + 2], h2a);
        h2a = fmaf(ha.w, wr[4 * k4 + 3], h2a);
        h2b = fmaf(hb.x, wr[4 * k4 + 0], h2b);
        h2b = fmaf(hb.y, wr[4 * k4 + 1], h2b);
        h2b = fmaf(hb.z, wr[4 * k4 + 2], h2b);
        h2b = fmaf(hb.w, wr[4 * k4 + 3], h2b);
    }
    h2a = fmaxf(h2a, 0.0f);
    h2b = fmaxf(h2b, 0.0f);

    float pa = h2a * w3s[lane];
    float pb = h2b * w3s[lane];
#pragma unroll
    for (int off = 16; off; off >>= 1) {
        pa += __shfl_xor_sync(FULLMASK, pa, off);
        pb += __shfl_xor_sync(FULLMASK, pb, off);
    }

    const float r = (lane & 1) ? pb : pa;
    if (lane < 2)
        out[b0 + e0 + lane] = tanhf(r + b3[0]);
}

// ---------------------------------------------------------------------------
extern "C" void kernel_launch(void* const* d_in, const int* in_sizes, int n_in,
                              void* d_out, int out_size) {
    const int*   indices = (const int*)  d_in[0];
    const float* emb     = (const float*)d_in[1];
    const float* w1      = (const float*)d_in[2];
    const float* b1      = (const float*)d_in[3];
    const float* w2      = (const float*)d_in[4];
    const float* b2      = (const float*)d_in[5];
    const float* w3      = (const float*)d_in[6];
    const float* b3      = (const float*)d_in[7];
    float* out = (float*)d_out;

    k1_precompute<<<INPUT_DIM / 128, 128>>>(emb, w1);                  // 384 blocks
    k2_forward<<<BATCH / 16, 256>>>(indices, b1, w2, b2, w3, b3, out); // 1024 blocks
}